// round 1
// baseline (speedup 1.0000x reference)
#include <cuda_runtime.h>
#include <cuda_bf16.h>
#include <cstddef>

// ---------------------------------------------------------------------------
// GraphSAGE: 3x (segment-mean aggregate + dual GEMM 128x128 + bias [+relu])
//            + final 128->64 linear.
// Strategy:
//   - Build CSR (by dst) once per call: count -> single-block chunked scan ->
//     atomic-cursor fill.  Turns the edge scatter into L2-resident gathers.
//   - Aggregation: one warp per node, float4 row loads, mean via 1/max(deg,1).
//   - GEMM: fused dual GEMM, fp32 via packed fma.rn.f32x2 (FFMA2, 2 FMA/lane).
//     Block = 256 thr, tile 128 nodes x OUTW outs, thread tile 8x8.
//     Weights staged in smem; value tiles stored transposed with XOR bank
//     swizzle (col = node ^ (f & 28)) -> conflict-free scalar writes,
//     broadcast float4 reads.
// ---------------------------------------------------------------------------

#define N_NODES 100000
#define N_EDGES 600000
#define F 128

// scratch (static __device__ allocations are allowed)
__device__ float g_hbuf0[(size_t)N_NODES * F];
__device__ float g_hbuf1[(size_t)N_NODES * F];
__device__ float g_agg[(size_t)N_NODES * F];
__device__ float g_invdeg[N_NODES];
__device__ int   g_deg[N_NODES];
__device__ int   g_cursor[N_NODES];
__device__ int   g_csr_off[N_NODES + 1];
__device__ int   g_csr_src[N_EDGES];

// ---- packed f32x2 helpers -------------------------------------------------
__device__ __forceinline__ unsigned long long ffma2(unsigned long long a,
                                                    unsigned long long b,
                                                    unsigned long long c) {
    unsigned long long d;
    asm("fma.rn.f32x2 %0, %1, %2, %3;" : "=l"(d) : "l"(a), "l"(b), "l"(c));
    return d;
}
__device__ __forceinline__ unsigned long long pack2(float x, float y) {
    unsigned long long d;
    asm("mov.b64 %0, {%1, %2};" : "=l"(d) : "f"(x), "f"(y));
    return d;
}
__device__ __forceinline__ float2 unpack2(unsigned long long v) {
    float2 r;
    asm("mov.b64 {%0, %1}, %2;" : "=f"(r.x), "=f"(r.y) : "l"(v));
    return r;
}

// ---- CSR build ------------------------------------------------------------
__global__ void init_kernel() {
    int i = blockIdx.x * blockDim.x + threadIdx.x;
    if (i < N_NODES) { g_deg[i] = 0; g_cursor[i] = 0; }
}

__global__ void count_kernel(const int* __restrict__ dst) {
    int e = blockIdx.x * blockDim.x + threadIdx.x;
    if (e < N_EDGES) atomicAdd(&g_deg[dst[e]], 1);
}

__global__ void scan_kernel() {
    __shared__ int tmp[1024];
    int tid = threadIdx.x;
    int carry = 0;
    for (int base = 0; base < N_NODES; base += 1024) {
        int idx = base + tid;
        int x = (idx < N_NODES) ? g_deg[idx] : 0;
        tmp[tid] = x;
        __syncthreads();
        #pragma unroll
        for (int off = 1; off < 1024; off <<= 1) {
            int v = (tid >= off) ? tmp[tid - off] : 0;
            __syncthreads();
            tmp[tid] += v;
            __syncthreads();
        }
        if (idx < N_NODES) {
            g_csr_off[idx] = carry + tmp[tid] - x;            // exclusive
            g_invdeg[idx] = 1.0f / fmaxf((float)x, 1.0f);
        }
        int tot = tmp[1023];
        __syncthreads();
        carry += tot;
    }
    if (tid == 0) g_csr_off[N_NODES] = carry;
}

__global__ void fill_kernel(const int* __restrict__ src,
                            const int* __restrict__ dst) {
    int e = blockIdx.x * blockDim.x + threadIdx.x;
    if (e < N_EDGES) {
        int d = dst[e];
        int pos = g_csr_off[d] + atomicAdd(&g_cursor[d], 1);
        g_csr_src[pos] = src[e];
    }
}

// ---- aggregation: warp per node, segment mean -----------------------------
__global__ void agg_kernel(const float* __restrict__ X) {
    int w = (blockIdx.x * blockDim.x + threadIdx.x) >> 5;
    int lane = threadIdx.x & 31;
    if (w >= N_NODES) return;
    int beg = g_csr_off[w];
    int end = g_csr_off[w + 1];
    float4 acc = make_float4(0.f, 0.f, 0.f, 0.f);
    for (int e = beg; e < end; e++) {
        int s = g_csr_src[e];
        const float4 v = *(const float4*)&X[(size_t)s * F + lane * 4];
        acc.x += v.x; acc.y += v.y; acc.z += v.z; acc.w += v.w;
    }
    float inv = g_invdeg[w];
    float4 r = make_float4(acc.x * inv, acc.y * inv, acc.z * inv, acc.w * inv);
    *(float4*)&g_agg[(size_t)w * F + lane * 4] = r;
}

// ---- fused (dual) GEMM + bias (+relu) -------------------------------------
// OUTW: 128 (hidden layers) or 64 (final).  DUAL: two GEMMs summed.
template <int OUTW, bool DUAL, bool RELU>
__global__ void __launch_bounds__(256) gemm_kernel(
    const float* __restrict__ X, const float* __restrict__ XN,
    const float* __restrict__ Ws, const float* __restrict__ bs,
    const float* __restrict__ Wn, const float* __restrict__ bn,
    float* __restrict__ Y) {
    constexpr int TXN = OUTW / 8;        // threads along outputs
    constexpr int TYN = 256 / TXN;       // threads along nodes
    constexpr int MBLK = TYN * 8;        // nodes per block (128 or 256)
    constexpr int KT = 32;               // k-chunk

    extern __shared__ float sm[];
    float* sWs = sm;                               // F*OUTW
    float* sWn = sWs + F * OUTW;                   // F*OUTW if DUAL
    float* sB  = sWn + (DUAL ? F * OUTW : 0);      // OUTW
    float* sHT = sB + OUTW;                        // KT*MBLK (transposed)
    float* sAT = sHT + KT * MBLK;                  // KT*MBLK if DUAL

    const int tid = threadIdx.x;
    const int tx = tid % TXN;
    const int ty = tid / TXN;
    const int node0 = blockIdx.x * MBLK;

    // stage weights + bias
    for (int i = tid; i < F * OUTW / 4; i += 256) {
        ((float4*)sWs)[i] = ((const float4*)Ws)[i];
        if (DUAL) ((float4*)sWn)[i] = ((const float4*)Wn)[i];
    }
    for (int i = tid; i < OUTW; i += 256)
        sB[i] = DUAL ? (bs[i] + bn[i]) : bs[i];

    unsigned long long acc[8][4];
    #pragma unroll
    for (int n = 0; n < 8; n++)
        #pragma unroll
        for (int p = 0; p < 4; p++) acc[n][p] = 0ULL;  // two packed 0.0f

    constexpr int NF4 = KT / 4;  // float4s per node per chunk
    for (int kc = 0; kc < F; kc += KT) {
        __syncthreads();  // previous chunk fully consumed / weights staged
        // load value tiles, transposed + XOR-swizzled (conflict-free writes)
        for (int idx = tid; idx < MBLK * NF4; idx += 256) {
            int node = idx / NF4;
            int f4 = idx % NF4;
            int gnode = node0 + node;
            float4 v = make_float4(0.f, 0.f, 0.f, 0.f);
            float4 va = v;
            if (gnode < N_NODES) {
                v = *(const float4*)&X[(size_t)gnode * F + kc + f4 * 4];
                if (DUAL) va = *(const float4*)&XN[(size_t)gnode * F + kc + f4 * 4];
            }
            #pragma unroll
            for (int j = 0; j < 4; j++) {
                int f = f4 * 4 + j;
                int col = node ^ (f & 28);
                sHT[f * MBLK + col] = (&v.x)[j];
                if (DUAL) sAT[f * MBLK + col] = (&va.x)[j];
            }
        }
        __syncthreads();

        #pragma unroll 4
        for (int i = 0; i < KT; i++) {
            const int row = kc + i;
            const float* wrow = &sWs[row * OUTW + tx * 8];
            ulonglong2 wsA = *(const ulonglong2*)wrow;
            ulonglong2 wsB = *(const ulonglong2*)(wrow + 4);
            unsigned long long w2[4] = {wsA.x, wsA.y, wsB.x, wsB.y};
            unsigned long long wn2[4];
            if (DUAL) {
                const float* wrow2 = &sWn[row * OUTW + tx * 8];
                ulonglong2 wnA = *(const ulonglong2*)wrow2;
                ulonglong2 wnB = *(const ulonglong2*)(wrow2 + 4);
                wn2[0] = wnA.x; wn2[1] = wnA.y; wn2[2] = wnB.x; wn2[3] = wnB.y;
            }
            const int s = i & 28;
            const float* hrow = &sHT[i * MBLK];
            float4 h0 = *(const float4*)&hrow[(ty * 8) ^ s];
            float4 h1 = *(const float4*)&hrow[(ty * 8 + 4) ^ s];
            float hv[8] = {h0.x, h0.y, h0.z, h0.w, h1.x, h1.y, h1.z, h1.w};
            float av[8];
            if (DUAL) {
                const float* arow = &sAT[i * MBLK];
                float4 a0 = *(const float4*)&arow[(ty * 8) ^ s];
                float4 a1 = *(const float4*)&arow[(ty * 8 + 4) ^ s];
                av[0] = a0.x; av[1] = a0.y; av[2] = a0.z; av[3] = a0.w;
                av[4] = a1.x; av[5] = a1.y; av[6] = a1.z; av[7] = a1.w;
            }
            #pragma unroll
            for (int n = 0; n < 8; n++) {
                unsigned long long hh = pack2(hv[n], hv[n]);
                #pragma unroll
                for (int p = 0; p < 4; p++)
                    acc[n][p] = ffma2(hh, w2[p], acc[n][p]);
                if (DUAL) {
                    unsigned long long aa = pack2(av[n], av[n]);
                    #pragma unroll
                    for (int p = 0; p < 4; p++)
                        acc[n][p] = ffma2(aa, wn2[p], acc[n][p]);
                }
            }
        }
    }

    // epilogue
    #pragma unroll
    for (int n = 0; n < 8; n++) {
        int gnode = node0 + ty * 8 + n;
        if (gnode >= N_NODES) continue;
        float out[8];
        #pragma unroll
        for (int p = 0; p < 4; p++) {
            float2 v = unpack2(acc[n][p]);
            out[2 * p] = v.x;
            out[2 * p + 1] = v.y;
        }
        #pragma unroll
        for (int k = 0; k < 8; k++) {
            float y = out[k] + sB[tx * 8 + k];
            if (RELU) y = fmaxf(y, 0.f);
            out[k] = y;
        }
        float4* d4 = (float4*)&Y[(size_t)gnode * OUTW + tx * 8];
        d4[0] = make_float4(out[0], out[1], out[2], out[3]);
        d4[1] = make_float4(out[4], out[5], out[6], out[7]);
    }
}

// ---------------------------------------------------------------------------
extern "C" void kernel_launch(void* const* d_in, const int* in_sizes, int n_in,
                              void* d_out, int out_size) {
    const float* feats = (const float*)d_in[0];
    const int* src = (const int*)d_in[1];
    const int* dst = (const int*)d_in[2];
    const float* Ws[3] = {(const float*)d_in[3], (const float*)d_in[7],
                          (const float*)d_in[11]};
    const float* bs[3] = {(const float*)d_in[4], (const float*)d_in[8],
                          (const float*)d_in[12]};
    const float* Wn[3] = {(const float*)d_in[5], (const float*)d_in[9],
                          (const float*)d_in[13]};
    const float* bn[3] = {(const float*)d_in[6], (const float*)d_in[10],
                          (const float*)d_in[14]};
    const float* Wout = (const float*)d_in[15];
    const float* bout = (const float*)d_in[16];

    float *h0, *h1, *agg;
    cudaGetSymbolAddress((void**)&h0, g_hbuf0);
    cudaGetSymbolAddress((void**)&h1, g_hbuf1);
    cudaGetSymbolAddress((void**)&agg, g_agg);

    // smem sizes (floats): dual = 2*128*128 + 128 + 2*32*128; final = 128*64+64+32*256
    const int SMEM_DUAL = (2 * F * 128 + 128 + 2 * 32 * 128) * (int)sizeof(float);
    const int SMEM_FIN = (F * 64 + 64 + 32 * 256) * (int)sizeof(float);

    auto kRelu = gemm_kernel<128, true, true>;
    auto kNoRelu = gemm_kernel<128, true, false>;
    auto kFinal = gemm_kernel<64, false, false>;
    cudaFuncSetAttribute((const void*)kRelu,
                         cudaFuncAttributeMaxDynamicSharedMemorySize, SMEM_DUAL);
    cudaFuncSetAttribute((const void*)kNoRelu,
                         cudaFuncAttributeMaxDynamicSharedMemorySize, SMEM_DUAL);
    cudaFuncSetAttribute((const void*)kFinal,
                         cudaFuncAttributeMaxDynamicSharedMemorySize, SMEM_FIN);

    // CSR build
    init_kernel<<<(N_NODES + 255) / 256, 256>>>();
    count_kernel<<<(N_EDGES + 255) / 256, 256>>>(dst);
    scan_kernel<<<1, 1024>>>();
    fill_kernel<<<(N_EDGES + 255) / 256, 256>>>(src, dst);

    const int AGG_BLOCKS = (N_NODES * 32 + 255) / 256;
    const int GEMM_BLOCKS = (N_NODES + 127) / 128;   // MBLK=128
    const int FIN_BLOCKS = (N_NODES + 255) / 256;    // MBLK=256

    // layer 0: features -> h0 (relu)
    agg_kernel<<<AGG_BLOCKS, 256>>>(feats);
    kRelu<<<GEMM_BLOCKS, 256, SMEM_DUAL>>>(feats, agg, Ws[0], bs[0], Wn[0],
                                           bn[0], h0);
    // layer 1: h0 -> h1 (relu)
    agg_kernel<<<AGG_BLOCKS, 256>>>(h0);
    kRelu<<<GEMM_BLOCKS, 256, SMEM_DUAL>>>(h0, agg, Ws[1], bs[1], Wn[1], bn[1],
                                           h1);
    // layer 2: h1 -> h0 (no relu)
    agg_kernel<<<AGG_BLOCKS, 256>>>(h1);
    kNoRelu<<<GEMM_BLOCKS, 256, SMEM_DUAL>>>(h1, agg, Ws[2], bs[2], Wn[2],
                                             bn[2], h0);
    // final linear: h0 @ W_out + b_out -> d_out
    kFinal<<<FIN_BLOCKS, 256, SMEM_FIN>>>(h0, nullptr, Wout, bout, nullptr,
                                          nullptr, (float*)d_out);
}

// round 3
// speedup vs baseline: 2.2855x; 2.2855x over previous
#include <cuda_runtime.h>
#include <cuda_bf16.h>
#include <cstdint>
#include <cstddef>

// ---------------------------------------------------------------------------
// GraphSAGE on sm_100 (base target, no tcgen05):
//   CSR build (count -> multi-block scan -> fill)
//   3x [ segment-mean agg ; dual GEMM via mma.sync bf16 hi/lo split ; +relu ]
//   final 128->64 linear (same GEMM kernel, single source)
//
// Dual GEMM trick: X*Ws + XN*Wn == [X|XN] @ [Ws;Wn]  -> one GEMM, K=256.
// Precision: x = hi + lo (bf16 each); x*w ~ hi*whi + lo*whi + hi*wlo
//   (lo*lo dropped, ~2^-18 relative) -> 3 mma terms, fp32 accumulate.
// CTA: 256 thr, tile 128(M) x N_OUT, K chunked by 64.  Weights (split bf16)
// stay smem-resident for all chunks; A chunks double-buffered with
// register-staged gmem prefetch overlapping the MMA loop.
// ---------------------------------------------------------------------------

#define N_NODES 100000
#define N_EDGES 600000
#define F 128

// ---- scratch ---------------------------------------------------------------
__device__ float g_hbuf0[(size_t)N_NODES * F];
__device__ float g_hbuf1[(size_t)N_NODES * F];
__device__ float g_agg[(size_t)N_NODES * F];
__device__ float g_invdeg[N_NODES];
__device__ int   g_deg[N_NODES];
__device__ int   g_cursor[N_NODES];
__device__ int   g_csr_off[N_NODES + 1];
__device__ int   g_csr_src[N_EDGES];
__device__ int   g_part[128];
__device__ int   g_partoff[128];
// pre-split weights, bf16 [n][k]: layers 0..2: n in 0..127, k in 0..255
// (k<128 = W_self col, k>=128 = W_neigh col); final: n in 0..63, k in 0..127.
#define W_TOTAL (3 * 128 * 256 + 64 * 128)
__device__ __nv_bfloat16 g_whi[W_TOTAL];
__device__ __nv_bfloat16 g_wlo[W_TOTAL];

// ---- helpers ---------------------------------------------------------------
__device__ __forceinline__ uint32_t smem_u32(const void* p) {
    uint32_t a;
    asm("{ .reg .u64 t; cvta.to.shared.u64 t, %1; cvt.u32.u64 %0, t; }"
        : "=r"(a) : "l"(p));
    return a;
}
// pack: low half = a, high half = b
__device__ __forceinline__ uint32_t pk_bf16(float a, float b) {
    uint32_t r;
    asm("cvt.rn.bf16x2.f32 %0, %1, %2;" : "=r"(r) : "f"(b), "f"(a));
    return r;
}
__device__ __forceinline__ float lo_f(uint32_t p) {
    return __uint_as_float(p << 16);
}
__device__ __forceinline__ float hi_f(uint32_t p) {
    return __uint_as_float(p & 0xFFFF0000u);
}
__device__ __forceinline__ void mma16816(float* c, const uint32_t* a,
                                         const uint32_t* b) {
    asm volatile(
        "mma.sync.aligned.m16n8k16.row.col.f32.bf16.bf16.f32 "
        "{%0,%1,%2,%3}, {%4,%5,%6,%7}, {%8,%9}, {%0,%1,%2,%3};"
        : "+f"(c[0]), "+f"(c[1]), "+f"(c[2]), "+f"(c[3])
        : "r"(a[0]), "r"(a[1]), "r"(a[2]), "r"(a[3]), "r"(b[0]), "r"(b[1]));
}
__device__ __forceinline__ void ldsm4(uint32_t* r, uint32_t addr) {
    asm volatile(
        "ldmatrix.sync.aligned.m8n8.x4.shared.b16 {%0,%1,%2,%3}, [%4];"
        : "=r"(r[0]), "=r"(r[1]), "=r"(r[2]), "=r"(r[3]) : "r"(addr));
}
#define SWZ(o) ((o) ^ (((o) >> 3) & 0x70))

// ---- CSR build -------------------------------------------------------------
__global__ void init_kernel() {
    int i = blockIdx.x * blockDim.x + threadIdx.x;
    if (i < N_NODES) { g_deg[i] = 0; g_cursor[i] = 0; }
}
__global__ void count_kernel(const int* __restrict__ dst) {
    int e = blockIdx.x * blockDim.x + threadIdx.x;
    if (e < N_EDGES) atomicAdd(&g_deg[dst[e]], 1);
}
__global__ void blockscan_kernel() {
    __shared__ int ws[32];
    int tid = threadIdx.x, lane = tid & 31, w = tid >> 5;
    int i = blockIdx.x * 1024 + tid;
    int x = (i < N_NODES) ? g_deg[i] : 0;
    int inc = x;
    #pragma unroll
    for (int o = 1; o < 32; o <<= 1) {
        int v = __shfl_up_sync(0xFFFFFFFF, inc, o);
        if (lane >= o) inc += v;
    }
    if (lane == 31) ws[w] = inc;
    __syncthreads();
    if (w == 0) {
        int s = ws[lane];
        #pragma unroll
        for (int o = 1; o < 32; o <<= 1) {
            int v = __shfl_up_sync(0xFFFFFFFF, s, o);
            if (lane >= o) s += v;
        }
        ws[lane] = s;
    }
    __syncthreads();
    int base = (w == 0) ? 0 : ws[w - 1];
    if (i < N_NODES) g_csr_off[i] = base + inc - x;
    if (tid == 1023) g_part[blockIdx.x] = ws[31];
}
__global__ void partscan_kernel(int nparts) {
    __shared__ int ws[4];
    int tid = threadIdx.x, lane = tid & 31, w = tid >> 5;
    int x = (tid < nparts) ? g_part[tid] : 0;
    int inc = x;
    #pragma unroll
    for (int o = 1; o < 32; o <<= 1) {
        int v = __shfl_up_sync(0xFFFFFFFF, inc, o);
        if (lane >= o) inc += v;
    }
    if (lane == 31) ws[w] = inc;
    __syncthreads();
    if (tid == 0) {
        int s = 0;
        #pragma unroll
        for (int j = 0; j < 4; j++) { int t = ws[j]; ws[j] = s; s += t; }
    }
    __syncthreads();
    if (tid < nparts) g_partoff[tid] = ws[w] + inc - x;
}
__global__ void finalize_kernel() {
    int i = blockIdx.x * blockDim.x + threadIdx.x;
    if (i < N_NODES) {
        g_csr_off[i] += g_partoff[i >> 10];
        g_invdeg[i] = 1.0f / fmaxf((float)g_deg[i], 1.0f);
    }
    if (i == 0) g_csr_off[N_NODES] = N_EDGES;
}
__global__ void fill_kernel(const int* __restrict__ src,
                            const int* __restrict__ dst) {
    int e = blockIdx.x * blockDim.x + threadIdx.x;
    if (e < N_EDGES) {
        int d = dst[e];
        int pos = g_csr_off[d] + atomicAdd(&g_cursor[d], 1);
        g_csr_src[pos] = src[e];
    }
}

// ---- weight pre-split ------------------------------------------------------
__global__ void wconv_kernel(const float* w0s, const float* w0n,
                             const float* w1s, const float* w1n,
                             const float* w2s, const float* w2n,
                             const float* wo) {
    int idx = blockIdx.x * blockDim.x + threadIdx.x;
    if (idx >= W_TOTAL) return;
    float w;
    if (idx < 3 * 32768) {
        int l = idx >> 15, local = idx & 32767;
        int n = local >> 8, k = local & 255;
        const float* ws = (l == 0) ? w0s : (l == 1) ? w1s : w2s;
        const float* wn = (l == 0) ? w0n : (l == 1) ? w1n : w2n;
        w = (k < 128) ? ws[k * 128 + n] : wn[(k - 128) * 128 + n];
    } else {
        int local = idx - 3 * 32768;
        int n = local >> 7, k = local & 127;
        w = wo[k * 64 + n];
    }
    __nv_bfloat16 hi = __float2bfloat16(w);
    g_whi[idx] = hi;
    g_wlo[idx] = __float2bfloat16(w - __bfloat162float(hi));
}

// ---- aggregation: warp per node, segment mean ------------------------------
__global__ void agg_kernel(const float* __restrict__ X) {
    int w = (blockIdx.x * blockDim.x + threadIdx.x) >> 5;
    int lane = threadIdx.x & 31;
    if (w >= N_NODES) return;
    int beg = g_csr_off[w], end = g_csr_off[w + 1];
    float4 acc = make_float4(0.f, 0.f, 0.f, 0.f);
    for (int e = beg; e < end; e++) {
        int s = g_csr_src[e];
        float4 v = *(const float4*)&X[(size_t)s * F + lane * 4];
        acc.x += v.x; acc.y += v.y; acc.z += v.z; acc.w += v.w;
    }
    float inv = g_invdeg[w];
    *(float4*)&g_agg[(size_t)w * F + lane * 4] =
        make_float4(acc.x * inv, acc.y * inv, acc.z * inv, acc.w * inv);
}

// ---- mma.sync bf16-split GEMM ---------------------------------------------
// Y[128b x N_OUT] = [X | XN] @ Whi/Wlo-split + bias (+relu)
template <int N_OUT, bool DUAL, bool RELU>
__global__ void __launch_bounds__(256) sage_mma(
    const float* __restrict__ X, const float* __restrict__ XN,
    const __nv_bfloat16* __restrict__ Whi,
    const __nv_bfloat16* __restrict__ Wlo,
    const float* __restrict__ bsv, const float* __restrict__ bnv,
    float* __restrict__ Y) {
    constexpr int KTOT = DUAL ? 256 : 128;
    constexpr int NCH = KTOT / 64;            // K chunks of 64
    constexpr int NWN = N_OUT / 32;           // warps along N (4 or 2)
    constexpr int MI = 128 / (8 / NWN) / 16;  // m16 frags per warp (4 or 2)
    constexpr int OFF_B = 65536;              // after 2 A double-buffers
    constexpr int BMAT = NCH * N_OUT * 128;   // bytes per split-mat
    constexpr int OFF_BIAS = OFF_B + 2 * BMAT;

    extern __shared__ char smc[];
    const uint32_t sb = smem_u32(smc);
    const int tid = threadIdx.x, wid = tid >> 5, lane = tid & 31;
    const int node0 = blockIdx.x * 128;
    float* sB = (float*)(smc + OFF_BIAS);
    if (tid < N_OUT) sB[tid] = bsv[tid] + (DUAL ? bnv[tid] : 0.0f);

    // B: smem-resident for all chunks (hi then lo), SW128-swizzled 128B rows
    #pragma unroll 1
    for (int m = 0; m < 2; m++) {
        const __nv_bfloat16* W = m ? Wlo : Whi;
        for (int idx = tid; idx < N_OUT * KTOT / 8; idx += 256) {
            int n = idx / (KTOT / 8);
            int k = (idx % (KTOT / 8)) * 8;
            uint4 v = *(const uint4*)(W + n * KTOT + k);
            uint32_t off = (uint32_t)(n * 128 + (k & 63) * 2);
            off = SWZ(off);
            *(uint4*)(smc + OFF_B + m * BMAT + (k >> 6) * (N_OUT * 128) + off) = v;
        }
    }

    // A producer state
    float4 st[8];
    const int arow = tid >> 1;
    const int acolb = (tid & 1) * 32;
    const int pnode = node0 + arow;
    auto do_ldg = [&](int c) {
        const float* src = (DUAL && c >= 2) ? (XN + (c - 2) * 64) : (X + c * 64);
        if (pnode < N_NODES) {
            const float4* p = (const float4*)(src + (size_t)pnode * F + acolb);
            #pragma unroll
            for (int j = 0; j < 8; j++) st[j] = p[j];
        } else {
            #pragma unroll
            for (int j = 0; j < 8; j++) st[j] = make_float4(0.f, 0.f, 0.f, 0.f);
        }
    };
    auto do_sts = [&](int b) {
        char* dhi = smc + b * 32768;
        char* dlo = dhi + 16384;
        #pragma unroll
        for (int j = 0; j < 4; j++) {
            float4 v0 = st[2 * j], v1 = st[2 * j + 1];
            uint4 H, L;
            H.x = pk_bf16(v0.x, v0.y); H.y = pk_bf16(v0.z, v0.w);
            H.z = pk_bf16(v1.x, v1.y); H.w = pk_bf16(v1.z, v1.w);
            L.x = pk_bf16(v0.x - lo_f(H.x), v0.y - hi_f(H.x));
            L.y = pk_bf16(v0.z - lo_f(H.y), v0.w - hi_f(H.y));
            L.z = pk_bf16(v1.x - lo_f(H.z), v1.y - hi_f(H.z));
            L.w = pk_bf16(v1.z - lo_f(H.w), v1.w - hi_f(H.w));
            uint32_t off = (uint32_t)(arow * 128 + (acolb + 8 * j) * 2);
            off = SWZ(off);
            *(uint4*)(dhi + off) = H;
            *(uint4*)(dlo + off) = L;
        }
    };

    // lane-invariant ldmatrix bases
    const int wn = (wid % NWN) * 32;
    const int wm = (wid / NWN) * (MI * 16);
    const int ar = wm + (lane & 15);
    const uint32_t a_base = (uint32_t)(ar * 128 + (lane >> 4) * 16);
    const uint32_t a_mask = (uint32_t)((ar & 7) << 4);
    const int br = wn + (lane & 7) + ((lane >> 4) << 3);
    const uint32_t b_base = (uint32_t)(br * 128 + ((lane >> 3) & 1) * 16);
    const uint32_t b_mask = (uint32_t)((br & 7) << 4);

    float acc[MI][4][4];
    #pragma unroll
    for (int mi = 0; mi < MI; mi++)
        #pragma unroll
        for (int ni = 0; ni < 4; ni++)
            #pragma unroll
            for (int q = 0; q < 4; q++) acc[mi][ni][q] = 0.f;

    do_ldg(0);
    do_sts(0);
    __syncthreads();

    #pragma unroll 1
    for (int c = 0; c < NCH; c++) {
        if (c + 1 < NCH) do_ldg(c + 1);
        const uint32_t ahi = sb + (c & 1) * 32768;
        const uint32_t alo = ahi + 16384;
        const uint32_t bb = sb + OFF_B + c * (N_OUT * 128);
        #pragma unroll
        for (int ks = 0; ks < 4; ks++) {
            uint32_t ah[MI][4], al[MI][4], bh[4][2], bl[4][2];
            uint32_t ka = (a_base + ks * 32) ^ a_mask;
            #pragma unroll
            for (int mi = 0; mi < MI; mi++) {
                ldsm4(ah[mi], ahi + ka + mi * 2048);
                ldsm4(al[mi], alo + ka + mi * 2048);
            }
            uint32_t kb = (b_base + ks * 32) ^ b_mask;
            ldsm4(&bh[0][0], bb + kb);
            ldsm4(&bh[2][0], bb + kb + 2048);
            ldsm4(&bl[0][0], bb + BMAT + kb);
            ldsm4(&bl[2][0], bb + BMAT + kb + 2048);
            #pragma unroll
            for (int mi = 0; mi < MI; mi++)
                #pragma unroll
                for (int ni = 0; ni < 4; ni++)
                    mma16816(acc[mi][ni], ah[mi], bh[ni]);
            #pragma unroll
            for (int mi = 0; mi < MI; mi++)
                #pragma unroll
                for (int ni = 0; ni < 4; ni++)
                    mma16816(acc[mi][ni], al[mi], bh[ni]);
            #pragma unroll
            for (int mi = 0; mi < MI; mi++)
                #pragma unroll
                for (int ni = 0; ni < 4; ni++)
                    mma16816(acc[mi][ni], ah[mi], bl[ni]);
        }
        if (c + 1 < NCH) {
            do_sts((c + 1) & 1);
            __syncthreads();
        }
    }

    // epilogue
    const int erow = wm + (lane >> 2);
    const int ecol = wn + (lane & 3) * 2;
    #pragma unroll
    for (int mi = 0; mi < MI; mi++) {
        #pragma unroll
        for (int h = 0; h < 2; h++) {
            int gr = node0 + erow + mi * 16 + h * 8;
            if (gr >= N_NODES) continue;
            float* yp = Y + (size_t)gr * N_OUT;
            #pragma unroll
            for (int ni = 0; ni < 4; ni++) {
                float2 o;
                o.x = acc[mi][ni][2 * h] + sB[ecol + ni * 8];
                o.y = acc[mi][ni][2 * h + 1] + sB[ecol + ni * 8 + 1];
                if (RELU) { o.x = fmaxf(o.x, 0.f); o.y = fmaxf(o.y, 0.f); }
                *(float2*)(yp + ecol + ni * 8) = o;
            }
        }
    }
}

// ---------------------------------------------------------------------------
extern "C" void kernel_launch(void* const* d_in, const int* in_sizes, int n_in,
                              void* d_out, int out_size) {
    const float* feats = (const float*)d_in[0];
    const int* src = (const int*)d_in[1];
    const int* dst = (const int*)d_in[2];
    const float* Ws[3] = {(const float*)d_in[3], (const float*)d_in[7],
                          (const float*)d_in[11]};
    const float* bs[3] = {(const float*)d_in[4], (const float*)d_in[8],
                          (const float*)d_in[12]};
    const float* Wn[3] = {(const float*)d_in[5], (const float*)d_in[9],
                          (const float*)d_in[13]};
    const float* bn[3] = {(const float*)d_in[6], (const float*)d_in[10],
                          (const float*)d_in[14]};
    const float* Wout = (const float*)d_in[15];
    const float* bout = (const float*)d_in[16];

    float *h0, *h1, *agg;
    __nv_bfloat16 *whi, *wlo;
    cudaGetSymbolAddress((void**)&h0, g_hbuf0);
    cudaGetSymbolAddress((void**)&h1, g_hbuf1);
    cudaGetSymbolAddress((void**)&agg, g_agg);
    cudaGetSymbolAddress((void**)&whi, g_whi);
    cudaGetSymbolAddress((void**)&wlo, g_wlo);

    // smem: 64KB A bufs + 2*BMAT weights + bias
    const int SMEM_DUAL = 65536 + 2 * (4 * 128 * 128) + 512;    // 197,120
    const int SMEM_FIN  = 65536 + 2 * (2 * 64 * 128) + 256;     //  98,560

    auto kRelu = sage_mma<128, true, true>;
    auto kNoRelu = sage_mma<128, true, false>;
    auto kFinal = sage_mma<64, false, false>;
    cudaFuncSetAttribute((const void*)kRelu,
                         cudaFuncAttributeMaxDynamicSharedMemorySize, SMEM_DUAL);
    cudaFuncSetAttribute((const void*)kNoRelu,
                         cudaFuncAttributeMaxDynamicSharedMemorySize, SMEM_DUAL);
    cudaFuncSetAttribute((const void*)kFinal,
                         cudaFuncAttributeMaxDynamicSharedMemorySize, SMEM_FIN);

    // CSR build
    const int NPART = (N_NODES + 1023) / 1024;  // 98
    init_kernel<<<(N_NODES + 255) / 256, 256>>>();
    count_kernel<<<(N_EDGES + 255) / 256, 256>>>(dst);
    blockscan_kernel<<<NPART, 1024>>>();
    partscan_kernel<<<1, 128>>>(NPART);
    finalize_kernel<<<(N_NODES + 255) / 256, 256>>>();
    fill_kernel<<<(N_EDGES + 255) / 256, 256>>>(src, dst);

    // weight pre-split
    wconv_kernel<<<(W_TOTAL + 255) / 256, 256>>>(Ws[0], Wn[0], Ws[1], Wn[1],
                                                 Ws[2], Wn[2], Wout);

    const int AGG_BLOCKS = (N_NODES * 32 + 255) / 256;
    const int GB = (N_NODES + 127) / 128;  // 782

    agg_kernel<<<AGG_BLOCKS, 256>>>(feats);
    kRelu<<<GB, 256, SMEM_DUAL>>>(feats, agg, whi, wlo, bs[0], bn[0], h0);
    agg_kernel<<<AGG_BLOCKS, 256>>>(h0);
    kRelu<<<GB, 256, SMEM_DUAL>>>(h0, agg, whi + 32768, wlo + 32768, bs[1],
                                  bn[1], h1);
    agg_kernel<<<AGG_BLOCKS, 256>>>(h1);
    kNoRelu<<<GB, 256, SMEM_DUAL>>>(h1, agg, whi + 65536, wlo + 65536, bs[2],
                                    bn[2], h0);
    kFinal<<<GB, 256, SMEM_FIN>>>(h0, nullptr, whi + 98304, wlo + 98304, bout,
                                  nullptr, (float*)d_out);
}